// round 7
// baseline (speedup 1.0000x reference)
#include <cuda_runtime.h>
#include <math.h>

// ---------------- problem constants ----------------
#define B       2
#define C       128
#define H0      384
#define W0      512
#define H1      192
#define W1      256
#define N0      (H0*W0)     // 196608
#define N1      (H1*W1)     // 49152
#define K_KP    512
#define K_MATCH 128
#define CAP     32768
#define MKEEP   4096
#define THRESH  0.7f
#define INVTEMP 512.0f

// ---------------- device scratch ----------------
__device__ float g_cand_score[4][CAP];
__device__ int   g_cand_idx[4][CAP];
__device__ int   g_cand_count[4];          // zeroed by gather for next replay
__device__ int   g_match_done;             // zeroed by the last match block
__device__ float g_kp_score[4][K_KP];
__device__ int   g_kp_idx[4][K_KP];
__device__ float g_desc[4][C][K_KP];       // gathered desc * score
__device__ float g_loc[4][2][K_KP];        // [row][{r,c}][k]
__device__ float g_M[C][C];                // Wq^T * Wk
__device__ float g_T[B][C][K_KP];          // M @ d2  (k-side transformed)
__device__ float g_rel[B][K_KP][K_KP];
__device__ float g_ratio[B][K_KP];
__device__ float g_y[B][2][K_KP];

// ---------------- kernels ----------------

// Fused score + 3x3 NMS over all 8 slices; z==8 plane computes M = Wq^T Wk.
__global__ void score_all_kernel(const float* __restrict__ rep10, const float* __restrict__ rel10,
                                 const float* __restrict__ rep11, const float* __restrict__ rel11,
                                 const float* __restrict__ rep20, const float* __restrict__ rel20,
                                 const float* __restrict__ rep21, const float* __restrict__ rel21,
                                 const float* __restrict__ Wq,  const float* __restrict__ Wk) {
    int z = blockIdx.z;
    if (z == 8) {
        // M[c1][c2] = sum_r Wq[r][c1] * Wk[r][c2]; 32x32 tile per block
        int mb = blockIdx.y * gridDim.x + blockIdx.x;
        if (mb >= 16) return;
        int c1_0 = (mb >> 2) * 32, c2_0 = (mb & 3) * 32;
        __shared__ float wqs[32][33];
        __shared__ float wks[32][33];
        int tid = threadIdx.x;               // 256
        int c1l = tid >> 3;
        int c2q = (tid & 7) * 4;
        float acc[4] = {0.f, 0.f, 0.f, 0.f};
        for (int r0 = 0; r0 < C; r0 += 32) {
            for (int i = tid; i < 32 * 32; i += 256) {
                int rr = i >> 5, cc = i & 31;
                wqs[rr][cc] = Wq[(r0 + rr) * C + c1_0 + cc];
                wks[rr][cc] = Wk[(r0 + rr) * C + c2_0 + cc];
            }
            __syncthreads();
            #pragma unroll
            for (int rr = 0; rr < 32; ++rr) {
                float wq = wqs[rr][c1l];
                #pragma unroll
                for (int j = 0; j < 4; ++j) acc[j] += wq * wks[rr][c2q + j];
            }
            __syncthreads();
        }
        #pragma unroll
        for (int j = 0; j < 4; ++j) g_M[c1_0 + c1l][c2_0 + c2q + j] = acc[j];
        return;
    }

    int img  = z >> 2;
    int scal = (z >> 1) & 1;
    int b    = z & 1;
    const float *rep, *rel;
    int H, W, nOff;
    if (scal == 0) { rep = img ? rep20 : rep10; rel = img ? rel20 : rel10; H = H0; W = W0; nOff = 0;  }
    else           { rep = img ? rep21 : rep11; rel = img ? rel21 : rel11; H = H1; W = W1; nOff = N0; }
    int gx0 = blockIdx.x * 128, gy0 = blockIdx.y * 8;
    if (gx0 >= W || gy0 >= H) return;
    int row = img * 2 + b;

    __shared__ float s[10][132];
    __shared__ float c_sc[1024];
    __shared__ int   c_ix[1024];
    __shared__ int   c_cnt, c_base;

    int tid = threadIdx.x;
    const float* repb = rep + b * (H * W);
    const float* relb = rel + b * (H * W);

    if (tid == 0) c_cnt = 0;
    for (int i = tid; i < 10 * 132; i += 256) {
        int ly = i / 132, lx = i - ly * 132;
        if (lx < 130) {
            int gy = gy0 + ly - 1, gx = gx0 + lx - 1;
            float v = -INFINITY;
            if (gy >= 0 && gy < H && gx >= 0 && gx < W) v = repb[gy * W + gx];
            s[ly][lx] = v;
        }
    }
    __syncthreads();

    int tx = tid & 31, ty = tid >> 5;     // 32 x 8, 4 px/thread
    int gy = gy0 + ty;
    int cx = tx * 4;
    float4 e4 = *(const float4*)&relb[gy * W + gx0 + cx];
    float ev[4] = {e4.x, e4.y, e4.z, e4.w};
    #pragma unroll
    for (int px = 0; px < 4; ++px) {
        float v = s[ty + 1][cx + px + 1];
        float mean = sqrtf(v * ev[px]);
        if (mean >= THRESH) {
            float nb = fmaxf(fmaxf(s[ty][cx + px],     s[ty][cx + px + 1]),
                             fmaxf(s[ty][cx + px + 2], s[ty + 1][cx + px]));
            nb = fmaxf(nb, fmaxf(fmaxf(s[ty + 1][cx + px + 2], s[ty + 2][cx + px]),
                                 fmaxf(s[ty + 2][cx + px + 1], s[ty + 2][cx + px + 2])));
            if (!(nb > v)) {
                int p = atomicAdd(&c_cnt, 1);
                c_sc[p] = mean;
                c_ix[p] = nOff + gy * W + gx0 + cx + px;
            }
        }
    }
    __syncthreads();
    int cnt = c_cnt;
    if (cnt == 0) return;
    if (tid == 0) c_base = atomicAdd(&g_cand_count[row], cnt);
    __syncthreads();
    int base = c_base;
    for (int i = tid; i < cnt; i += 256) {
        int pos = base + i;
        if (pos < CAP) {
            g_cand_score[row][pos] = c_sc[i];
            g_cand_idx[row][pos]   = c_ix[i];
        }
    }
}

// per-row top-512: histogram prune (parallel suffix scan) + exact rank-count
__global__ void topk_kernel() {
    __shared__ int   hist[1024];
    __shared__ int   sA[1024];
    __shared__ int   sB[1024];
    __shared__ float ks_[MKEEP];
    __shared__ int   ki_[MKEEP];
    __shared__ int   s_thr, s_keep;
    int row = blockIdx.x;
    int tid = threadIdx.x;              // 1024 threads
    int count = g_cand_count[row];
    if (count > CAP) count = CAP;

    hist[tid] = 0;
    if (tid == 0) { s_thr = 0; s_keep = 0; }
    __syncthreads();

    const float SCL = 1024.0f / 0.3f;
    for (int i = tid; i < count; i += 1024) {
        float sc = g_cand_score[row][i];
        int bb = (int)((sc - THRESH) * SCL);
        bb = max(0, min(1023, bb));
        atomicAdd(&hist[bb], 1);
    }
    __syncthreads();

    // parallel inclusive SUFFIX scan: sA[i] = sum(hist[i..1023]) in 10 steps
    sA[tid] = hist[tid];
    __syncthreads();
    #pragma unroll
    for (int off = 1; off < 1024; off <<= 1) {
        int v = sA[tid] + ((tid + off < 1024) ? sA[tid + off] : 0);
        __syncthreads();
        sB[tid] = v;
        __syncthreads();
        int t2 = sB[tid];            // copy back (ping-pong unrolled as 2 arrays)
        sA[tid] = t2;
        __syncthreads();
    }
    {
        int cge = sA[tid];
        int cge_next = (tid < 1023) ? sA[tid + 1] : 0;
        if (cge >= K_KP && cge_next < K_KP) s_thr = tid;   // unique writer
    }
    __syncthreads();

    int thr = s_thr;
    for (int i = tid; i < count; i += 1024) {
        float sc = g_cand_score[row][i];
        int bb = (int)((sc - THRESH) * SCL);
        bb = max(0, min(1023, bb));
        if (bb >= thr) {
            int p = atomicAdd(&s_keep, 1);
            if (p < MKEEP) { ks_[p] = sc; ki_[p] = g_cand_idx[row][i]; }
        }
    }
    __syncthreads();
    int kept = min(s_keep, MKEEP);

    for (int i = tid; i < kept; i += 1024) {
        float si = ks_[i]; int ii = ki_[i];
        int rank = 0;
        for (int j = 0; j < kept; ++j) {
            float sj = ks_[j];
            rank += (sj > si) || (sj == si && ki_[j] < ii);
        }
        if (rank < K_KP) { g_kp_score[row][rank] = si; g_kp_idx[row][rank] = ii; }
    }
    __syncthreads();
    if (kept < K_KP) {
        for (int r2 = kept + tid; r2 < K_KP; r2 += 1024) {
            g_kp_score[row][r2] = -1.0f;
            g_kp_idx[row][r2]   = r2 - kept;
        }
    }
}

// Scattered gather for all 4 rows; block 0 also resets candidate counters.
__global__ void gather_kernel(const float* __restrict__ d1s0, const float* __restrict__ d1s1,
                              const float* __restrict__ d2s0, const float* __restrict__ d2s1) {
    int bid = blockIdx.x;
    if (bid == 0 && threadIdx.x < 4) g_cand_count[threadIdx.x] = 0;
    int row = bid >> 8;                               // 256 blocks per row
    int t   = (bid & 255) * 256 + threadIdx.x;        // over C*K_KP, kpos fastest
    int ch  = t >> 9;
    int kp  = t & (K_KP - 1);
    int img = row >> 1, b = row & 1;

    int   idx = g_kp_idx[row][kp];
    float sc  = g_kp_score[row][kp];

    const float* dsc; int HW, p;
    if (idx < N0) { dsc = img ? d2s0 : d1s0; HW = N0; p = idx; }
    else          { dsc = img ? d2s1 : d1s1; HW = N1; p = idx - N0; }
    g_desc[row][ch][kp] = __ldg(&dsc[(b * C + ch) * HW + p]) * sc;

    if (ch < 2) {
        int W, pp; float scale;
        if (idx < N0) { W = W0; pp = idx;      scale = 1.0f; }
        else          { W = W1; pp = idx - N0; scale = 2.0f; }
        int r = pp / W, c = pp - r * W;
        g_loc[row][ch][kp] = (ch == 0 ? (float)r : (float)c) * scale;
    }
}

// T[b] = M @ d2 : 16r x 64n tile, 512 threads (2 outputs/thread), grid (8,8,2)
__global__ void tk_kernel() {
    __shared__ float ms[32][17];   // [c][r]
    __shared__ float ds[32][64];   // [c][n]
    int n0 = blockIdx.x * 64, r0 = blockIdx.y * 16, b = blockIdx.z;
    int krow = 2 + b;
    int tid = threadIdx.x;              // 512
    int tx = tid & 31, ty = tid >> 5;   // tx -> n pair, ty -> r (0..15)
    float a0 = 0.f, a1 = 0.f;

    for (int c0 = 0; c0 < C; c0 += 32) {
        {
            int rr = tid >> 5, cc = tid & 31;   // 512 = 16x32
            ms[cc][rr] = g_M[r0 + rr][c0 + cc];
        }
        for (int i = tid; i < 32 * 64; i += 512) {
            int cc = i >> 6, nn = i & 63;
            ds[cc][nn] = g_desc[krow][c0 + cc][n0 + nn];
        }
        __syncthreads();
        #pragma unroll
        for (int cc = 0; cc < 32; ++cc) {
            float w = ms[cc][ty];
            float2 dv = *(const float2*)&ds[cc][tx * 2];
            a0 += w * dv.x;
            a1 += w * dv.y;
        }
        __syncthreads();
    }
    g_T[b][r0 + ty][n0 + tx * 2 + 0] = a0;
    g_T[b][r0 + ty][n0 + tx * 2 + 1] = a1;
}

// rel[b][n][m] = sum_c d1[b][c][n] * T[b][c][m]; 64x64 tile, 512 threads
__global__ void rel_kernel() {
    __shared__ float qs[32][64];
    __shared__ float ks2[32][64];
    int b  = blockIdx.z;
    int n0 = blockIdx.y * 64, m0 = blockIdx.x * 64;
    int tid = threadIdx.x;              // 512
    int tx = tid & 15, ty = tid >> 4;   // tx -> m quad, ty -> n pair (0..31)
    float acc[2][4];
    #pragma unroll
    for (int i = 0; i < 2; ++i)
        #pragma unroll
        for (int j = 0; j < 4; ++j) acc[i][j] = 0.0f;

    for (int c0 = 0; c0 < C; c0 += 32) {
        for (int i = tid; i < 32 * 64; i += 512) {
            int cc = i >> 6, nn = i & 63;
            qs[cc][nn]  = g_desc[b][c0 + cc][n0 + nn];
            ks2[cc][nn] = g_T[b][c0 + cc][m0 + nn];
        }
        __syncthreads();
        #pragma unroll
        for (int cc = 0; cc < 32; ++cc) {
            float2 qv = *(const float2*)&qs[cc][ty * 2];
            float4 kv = *(const float4*)&ks2[cc][tx * 4];
            float qa[2] = {qv.x, qv.y};
            float ka[4] = {kv.x, kv.y, kv.z, kv.w};
            #pragma unroll
            for (int i = 0; i < 2; ++i)
                #pragma unroll
                for (int j = 0; j < 4; ++j) acc[i][j] += qa[i] * ka[j];
        }
        __syncthreads();
    }
    #pragma unroll
    for (int i = 0; i < 2; ++i)
        #pragma unroll
        for (int j = 0; j < 4; ++j)
            g_rel[b][n0 + ty * 2 + i][m0 + tx * 4 + j] = acc[i][j];
}

// per-row: one-pass top2 + acos ratio + softmax-weighted loc; the LAST block
// (threadfence+atomic) also performs the final top-128 selection.
__global__ void match_kernel(const float* __restrict__ Wv, float* __restrict__ out) {
    int b    = blockIdx.y;
    int warp = threadIdx.x >> 5, lane = threadIdx.x & 31;
    int n = blockIdx.x * 8 + warp;
    const float* relrow = &g_rel[b][n][0];

    float v[16];
    #pragma unroll
    for (int t = 0; t < 16; ++t) v[t] = relrow[lane + 32 * t];

    float m1 = -2.0f, m2 = -2.0f;
    #pragma unroll
    for (int t = 0; t < 16; ++t) {
        float x = v[t];
        if (x > m1) { m2 = m1; m1 = x; }
        else if (x > m2) m2 = x;
    }
    #pragma unroll
    for (int off = 16; off; off >>= 1) {
        float o1 = __shfl_down_sync(0xffffffffu, m1, off);
        float o2 = __shfl_down_sync(0xffffffffu, m2, off);
        if (o1 > m1) { m2 = fmaxf(m1, o2); m1 = o1; }
        else         { m2 = fmaxf(m2, o1); }
    }
    m1 = __shfl_sync(0xffffffffu, m1, 0);
    m2 = __shfl_sync(0xffffffffu, m2, 0);

    float wv00 = Wv[0], wv01 = Wv[1], wv10 = Wv[2], wv11 = Wv[3];
    int krow = 2 + b;
    float sw = 0.0f, y0 = 0.0f, y1 = 0.0f;
    #pragma unroll
    for (int t = 0; t < 16; ++t) {
        int m = lane + 32 * t;
        float w = expf(INVTEMP * (v[t] - m1));
        float l0 = g_loc[krow][0][m], l1 = g_loc[krow][1][m];
        sw += w;
        y0 += w * (wv00 * l0 + wv01 * l1);
        y1 += w * (wv10 * l0 + wv11 * l1);
    }
    #pragma unroll
    for (int off = 16; off; off >>= 1) {
        sw += __shfl_down_sync(0xffffffffu, sw, off);
        y0 += __shfl_down_sync(0xffffffffu, y0, off);
        y1 += __shfl_down_sync(0xffffffffu, y1, off);
    }
    if (lane == 0) {
        float a1 = acosf(fminf(fmaxf(m1, -1.0f), 1.0f));
        float a2 = acosf(fminf(fmaxf(m2, -1.0f), 1.0f));
        g_ratio[b][n] = a1 / a2;
        g_y[b][0][n] = y0 / sw;
        g_y[b][1][n] = y1 / sw;
    }

    // ---- last-block final top-128 (deterministic regardless of which block) ----
    __syncthreads();
    __threadfence();
    __shared__ int s_last;
    if (threadIdx.x == 0) {
        int done = atomicAdd(&g_match_done, 1);
        s_last = (done == (K_KP / 8) * B - 1) ? 1 : 0;
    }
    __syncthreads();
    if (!s_last) return;
    if (threadIdx.x == 0) g_match_done = 0;    // reset for next replay
    __threadfence();

    __shared__ float rs[K_KP];
    for (int b2 = 0; b2 < B; ++b2) {
        for (int i = threadIdx.x; i < K_KP; i += 256) rs[i] = g_ratio[b2][i];
        __syncthreads();
        for (int e = threadIdx.x; e < K_KP; e += 256) {
            float ri = rs[e];
            int rank = 0;
            for (int j = 0; j < K_KP; ++j) {
                float rj = rs[j];
                rank += (rj < ri) || (rj == ri && j < e);
            }
            if (rank < K_MATCH) {
                out[(b2 * 4 + 0) * K_MATCH + rank] = g_loc[b2][0][e];
                out[(b2 * 4 + 1) * K_MATCH + rank] = g_loc[b2][1][e];
                out[(b2 * 4 + 2) * K_MATCH + rank] = g_y[b2][0][e];
                out[(b2 * 4 + 3) * K_MATCH + rank] = g_y[b2][1][e];
            }
        }
        __syncthreads();
    }
}

// ---------------- launch ----------------
extern "C" void kernel_launch(void* const* d_in, const int* in_sizes, int n_in,
                              void* d_out, int out_size) {
    const float* rep1_s0 = (const float*)d_in[0];
    const float* rel1_s0 = (const float*)d_in[1];
    const float* desc1_s0 = (const float*)d_in[2];
    const float* rep1_s1 = (const float*)d_in[3];
    const float* rel1_s1 = (const float*)d_in[4];
    const float* desc1_s1 = (const float*)d_in[5];
    const float* rep2_s0 = (const float*)d_in[6];
    const float* rel2_s0 = (const float*)d_in[7];
    const float* desc2_s0 = (const float*)d_in[8];
    const float* rep2_s1 = (const float*)d_in[9];
    const float* rel2_s1 = (const float*)d_in[10];
    const float* desc2_s1 = (const float*)d_in[11];
    const float* Wq = (const float*)d_in[12];
    const float* Wk = (const float*)d_in[13];
    const float* Wv = (const float*)d_in[14];
    float* out = (float*)d_out;

    score_all_kernel<<<dim3(W0 / 128, H0 / 8, 9), 256>>>(
        rep1_s0, rel1_s0, rep1_s1, rel1_s1, rep2_s0, rel2_s0, rep2_s1, rel2_s1, Wq, Wk);

    topk_kernel<<<4, 1024>>>();

    gather_kernel<<<1024, 256>>>(desc1_s0, desc1_s1, desc2_s0, desc2_s1);

    tk_kernel<<<dim3(8, 8, 2), 512>>>();

    rel_kernel<<<dim3(8, 8, B), 512>>>();

    match_kernel<<<dim3(K_KP / 8, B), 256>>>(Wv, out);
}